// round 16
// baseline (speedup 1.0000x reference)
#include <cuda_runtime.h>
#include <math.h>

// Problem constants
#define CIN    128
#define CMID   16
#define COUT   256
#define HW     12544
#define WIDTH  112
#define NBLK   784
#define NTHR   512

// Pooling segments 16 -> 7 (overlapping avg pool)
__constant__ int   SEG_S[7] = {0, 2, 4, 6, 9, 11, 13};
__constant__ int   SEG_E[7] = {3, 5, 7, 10, 12, 14, 16};
__constant__ float SEG_I[7] = {1.f/3.f, 1.f/3.f, 1.f/3.f, 0.25f, 1.f/3.f, 1.f/3.f, 1.f/3.f};

// Inter-kernel scratch (static device allocations — allowed)
__device__ float g_agg[NBLK * 784];   // merged agg per block  [49][16]
__device__ float g_sv [NBLK * 256];   // per-pixel sigmoid
__device__ int   g_bm [NBLK * 256];   // per-pixel argmax cluster
__device__ int   g_flag[NBLK];        // 1 = block needs exact recheck

// ---- packed f32x2 helpers (sm_103a, PTX-only) ----
__device__ __forceinline__ unsigned long long pk2(float a, float b) {
    unsigned long long r;
    asm("mov.b64 %0, {%1, %2};" : "=l"(r) : "f"(a), "f"(b));
    return r;
}
__device__ __forceinline__ unsigned long long ffma2(unsigned long long a,
                                                    unsigned long long b,
                                                    unsigned long long c) {
    unsigned long long d;
    asm("fma.rn.f32x2 %0, %1, %2, %3;" : "=l"(d) : "l"(a), "l"(b), "l"(c));
    return d;
}
__device__ __forceinline__ unsigned long long fmul2(unsigned long long a,
                                                    unsigned long long b) {
    unsigned long long d;
    asm("mul.rn.f32x2 %0, %1, %2;" : "=l"(d) : "l"(a), "l"(b));
    return d;
}
__device__ __forceinline__ unsigned long long fadd2(unsigned long long a,
                                                    unsigned long long b) {
    unsigned long long d;
    asm("add.rn.f32x2 %0, %1, %2;" : "=l"(d) : "l"(a), "l"(b));
    return d;
}
__device__ __forceinline__ float2 upk(unsigned long long v) {
    float2 f;
    asm("mov.b64 {%0, %1}, %2;" : "=f"(f.x), "=f"(f.y) : "l"(v));
    return f;
}

#define SGNMASK 0x8000000080000000ULL
#define OFFSET_F 16384.0f

// Exact compensated accumulate (K1b only).
__device__ __forceinline__ void dfacc2(unsigned long long& hi, unsigned long long& lo,
                                       unsigned long long xd, unsigned long long w) {
    unsigned long long ph = fmul2(xd, w);
    unsigned long long pl = ffma2(xd, w, ph ^ SGNMASK);
    unsigned long long s  = fadd2(hi, ph);
    unsigned long long d  = fadd2(hi, s ^ SGNMASK);
    unsigned long long e  = fadd2(d, ph);
    lo = fadd2(lo, fadd2(e, pl));
    hi = s;
}

#define FSTR 257

// ================= Kernel 1: fp32 common path (3 CTAs/SM) =================
// smem float offsets
#define A_FS   0                       // float[16*257]
#define A_VS   (A_FS  + 16*FSTR)       // float[16*257]
#define A_WBUF (A_VS  + 16*FSTR)       // float[4096]: wsf/wsv -> vc/cf32
#define A_AGN  (A_WBUF + 4096)         // float[784]
#define A_AGD  (A_AGN + 784)           // float[52]
#define A_FBS  (A_AGD + 52)            // float[16]
#define A_VBS  (A_FBS + 16)            // float[16]
#define A_ZB1  (A_VBS + 16)            // float[512]
#define A_ZB2  (A_ZB1 + 512)           // float[512]
#define A_BMB  (A_ZB2 + 512)           // int[512]
#define SMEM1_BYTES ((A_BMB + 512) * 4)   // 58,896 B -> 3 CTAs/SM

extern "C" __global__ void __launch_bounds__(NTHR, 3)
lc_k1(const float* __restrict__ x,   const float* __restrict__ fw,
      const float* __restrict__ fb,  const float* __restrict__ vw,
      const float* __restrict__ vb,  const float* __restrict__ salpha,
      const float* __restrict__ sbeta)
{
    extern __shared__ float sm[];
    float* fs   = sm + A_FS;
    float* vs   = sm + A_VS;
    float* wbuf = sm + A_WBUF;
    float* agn  = sm + A_AGN;
    float* agd  = sm + A_AGD;
    float* fbs  = sm + A_FBS;
    float* vbs  = sm + A_VBS;
    float* zb1  = sm + A_ZB1;
    float* zb2  = sm + A_ZB2;
    int*   bmb  = (int*)(sm + A_BMB);
    float* wsf  = wbuf;
    float* wsv  = wbuf + 2048;
    float* vc   = wbuf;
    float* cf32 = wbuf + 784;

    const int t = threadIdx.x;
    const int b = blockIdx.x;
    const int batch = b / 49;
    const int g = b - batch * 49;
    const int gx = g / 7, gy = g - (g / 7) * 7;

    for (int i = t; i < 2048; i += NTHR) {
        int c = i >> 4, o = i & 15;
        wsf[i] = fw[o * CIN + c];
        wsv[i] = vw[o * CIN + c];
    }
    if (t < 16) { fbs[t] = fb[t]; vbs[t] = vb[t]; }
    for (int i = t; i < 784; i += NTHR) agn[i] = 0.f;
    if (t < 49) agd[t] = 0.f;
    __syncthreads();

    // ---- Stage A: warps 0-7 -> f, warps 8-15 -> v (1 pixel, 128 ch each) ----
    const int px  = t & 255;
    const int prj = t >> 8;
    const int apr = px >> 4, apc = px & 15;
    const float* xa = x + (size_t)batch * COUT * HW + (size_t)prj * CIN * HW
                        + (size_t)(gx * 16 + apr) * WIDTH + (gy * 16 + apc);
    const float* wsel = prj ? wsv : wsf;
    {
        unsigned long long acc[8];
        #pragma unroll
        for (int j = 0; j < 8; j++) acc[j] = 0ull;
        #pragma unroll 8
        for (int c = 0; c < CIN; c++) {
            float xv = __ldg(xa + (size_t)c * HW);
            unsigned long long xd = pk2(xv, xv);
            const ulonglong2* wr = (const ulonglong2*)(wsel + c * 16);
            #pragma unroll
            for (int j = 0; j < 4; j++) {
                ulonglong2 a = wr[j];
                acc[2*j]   = ffma2(xd, a.x, acc[2*j]);
                acc[2*j+1] = ffma2(xd, a.y, acc[2*j+1]);
            }
        }
        float* dst = prj ? vs : fs;
        const float* bsel = prj ? vbs : fbs;
        #pragma unroll
        for (int j = 0; j < 8; j++) {
            float2 v = upk(acc[j]);
            dst[(2*j)   * FSTR + px] = v.x + bsel[2*j];
            dst[(2*j+1) * FSTR + px] = v.y + bsel[2*j+1];
        }
    }
    __syncthreads();

    // ---- Stage B: fp32 pooling ----
    for (int it = t; it < 1568; it += NTHR) {
        int half = it >= 784;
        int rem = half ? it - 784 : it;
        int m = rem >> 4, cc = rem & 15;
        int i = m / 7, jj = m - i * 7;
        const float* src = half ? vs : fs;
        float ssum = 0.f;
        for (int r = SEG_S[i]; r < SEG_E[i]; r++)
            for (int q = SEG_S[jj]; q < SEG_E[jj]; q++)
                ssum += src[cc * FSTR + r * 16 + q];
        ssum *= SEG_I[i] * SEG_I[jj];
        if (half) vc[rem] = ssum; else cf32[rem] = ssum;
    }
    __syncthreads();

    if (t < 49) {
        float ss = 0.f;
        #pragma unroll
        for (int cc = 0; cc < 16; cc++) {
            float v = cf32[t*16+cc];
            ss = __fmaf_rn(v, v, ss);
        }
        float inv = 1.f / fmaxf(sqrtf(ss), 1e-12f);
        #pragma unroll
        for (int cc = 0; cc < 16; cc++) cf32[t*16+cc] *= inv;
    }
    __syncthreads();

    // ---- Stage C: split-cluster scan (all 512 threads) ----
    const float alphaf = __ldg(salpha);
    const float betaf  = __ldg(sbeta);
    {
        float ffn[16];
        float ss = 0.f;
        #pragma unroll
        for (int cc = 0; cc < 16; cc++) {
            float v = fs[cc * FSTR + px];
            ffn[cc] = v;
            ss = __fmaf_rn(v, v, ss);
        }
        float inv = 1.f / fmaxf(sqrtf(ss), 1e-12f);
        #pragma unroll
        for (int cc = 0; cc < 16; cc++) ffn[cc] *= inv;

        float z1h = -1e30f, z2h = -1e30f;
        int bmh = 0;
        const int mstart = prj ? 25 : 0;
        const int mend   = prj ? 49 : 25;
        for (int m = mstart; m < mend; m++) {
            const float4* cr = (const float4*)(cf32 + m * 16);
            float dot = 0.f;
            #pragma unroll
            for (int q = 0; q < 4; q++) {
                float4 w = cr[q];
                dot = __fmaf_rn(w.x, ffn[4*q+0], dot);
                dot = __fmaf_rn(w.y, ffn[4*q+1], dot);
                dot = __fmaf_rn(w.z, ffn[4*q+2], dot);
                dot = __fmaf_rn(w.w, ffn[4*q+3], dot);
            }
            float z = betaf + alphaf * dot;
            if (z > z1h) { z2h = z1h; z1h = z; bmh = m; }
            else if (z > z2h) { z2h = z; }
        }
        zb1[t] = z1h; zb2[t] = z2h; bmb[t] = bmh;
    }
    __syncthreads();

    float z1 = 1e30f, z2 = 0.f;
    int bm = 0;
    float s = 0.f;
    if (t < 256) {
        float a1 = zb1[t],       a2 = zb2[t];       int abm = bmb[t];
        float b1 = zb1[t + 256], b2 = zb2[t + 256]; int bbm = bmb[t + 256];
        if (a1 >= b1) { z1 = a1; bm = abm; z2 = fmaxf(a2, b1); }
        else          { z1 = b1; bm = bbm; z2 = fmaxf(b2, a1); }
        s = 1.f / (1.f + expf(-z1));
    }

    // ---- vote -> flag (exact recheck handled by lc_k1b) ----
    int risk = __syncthreads_or((t < 256) && (z1 - z2) < 1e-4f);
    if (t == 0) g_flag[b] = risk;

    // ---- share (s, bm); split atomics ----
    if (t < 256) { zb1[t] = s; bmb[t] = bm; }
    __syncthreads();
    {
        float sv = zb1[px];
        int bmv = bmb[px];
        if (t < 256) atomicAdd(&agd[bmv], sv);
        const int cc0 = prj ? 8 : 0;
        #pragma unroll
        for (int cc = 0; cc < 8; cc++)
            atomicAdd(&agn[bmv * 16 + cc0 + cc], sv * vs[(cc0 + cc) * FSTR + px]);
    }
    __syncthreads();

    for (int it = t; it < 784; it += NTHR) {
        int m = it >> 4;
        g_agg[(size_t)b * 784 + it] = (agn[it] + vc[it]) / (agd[m] + 1.f);
    }
    if (t < 256) {
        g_sv[b * 256 + t] = s;
        g_bm[b * 256 + t] = bm;
    }
}

// ============ Kernel 1b: exact recheck for flagged blocks only ============
// smem byte offsets
#define B_FSD  0                               // double[16*257] = 32,896
#define B_CFD  (B_FSD + 16*FSTR*8)             // double[784]
#define B_W    (B_CFD + 784*8)                 // float[4096]: fw2 / wsv2
#define B_VS   (B_W   + 4096*4)                // float[16*257]
#define B_VC   (B_VS  + 16*FSTR*4)             // float[784]
#define B_CF32 (B_VC  + 784*4)                 // float[784]
#define B_AGN  (B_CF32 + 784*4)                // float[784]
#define B_AGD  (B_AGN + 784*4)                 // float[52]
#define B_FBS  (B_AGD + 52*4)                  // float[16]
#define B_VBS  (B_FBS + 16*4)                  // float[16]
#define SMEM1B_BYTES (B_VBS + 16*4)            // 81,744 B

extern "C" __global__ void __launch_bounds__(NTHR, 2)
lc_k1b(const float* __restrict__ x,   const float* __restrict__ fw,
       const float* __restrict__ fb,  const float* __restrict__ vw,
       const float* __restrict__ vb,  const float* __restrict__ salpha,
       const float* __restrict__ sbeta)
{
    const int b = blockIdx.x;
    if (g_flag[b] == 0) return;       // uniform across the CTA; no syncs yet

    extern __shared__ char smraw[];
    double* fsd  = (double*)(smraw + B_FSD);
    double* cfd  = (double*)(smraw + B_CFD);
    float*  fw2  = (float*)(smraw + B_W);
    float*  wsv2 = (float*)(smraw + B_W) + 2048;
    float*  vs   = (float*)(smraw + B_VS);
    float*  vc   = (float*)(smraw + B_VC);
    float*  cf32 = (float*)(smraw + B_CF32);
    float*  agn  = (float*)(smraw + B_AGN);
    float*  agd  = (float*)(smraw + B_AGD);
    float*  fbs  = (float*)(smraw + B_FBS);
    float*  vbs  = (float*)(smraw + B_VBS);

    const int t = threadIdx.x;
    const int batch = b / 49;
    const int g = b - batch * 49;
    const int gx = g / 7, gy = g - (g / 7) * 7;
    const int px  = t & 255;
    const int prj = t >> 8;
    const int apr = px >> 4, apc = px & 15;

    for (int i = t; i < 2048; i += NTHR) {
        int c = i >> 4, o = i & 15;
        fw2[i]  = fw[o * CIN + c];
        wsv2[i] = vw[o * CIN + c];
    }
    if (t < 16) { fbs[t] = fb[t]; vbs[t] = vb[t]; }
    for (int i = t; i < 784; i += NTHR) agn[i] = 0.f;
    if (t < 49) agd[t] = 0.f;
    __syncthreads();

    // lower half: exact f via dfacc2 -> fsd ; upper half: v fp32 -> vs
    const float* xa = x + (size_t)batch * COUT * HW + (size_t)prj * CIN * HW
                        + (size_t)(gx * 16 + apr) * WIDTH + (gy * 16 + apc);
    if (prj == 0) {
        unsigned long long fhi[8], flo[8];
        #pragma unroll
        for (int j = 0; j < 8; j++) { fhi[j] = pk2(OFFSET_F, OFFSET_F); flo[j] = 0ull; }
        #pragma unroll 4
        for (int c = 0; c < CIN; c++) {
            float x1 = __ldg(xa + (size_t)c * HW);
            unsigned long long x1d = pk2(x1, x1);
            const ulonglong2* wf = (const ulonglong2*)(fw2 + c * 16);
            #pragma unroll
            for (int j = 0; j < 4; j++) {
                ulonglong2 a = wf[j];
                dfacc2(fhi[2*j],   flo[2*j],   x1d, a.x);
                dfacc2(fhi[2*j+1], flo[2*j+1], x1d, a.y);
            }
        }
        #pragma unroll
        for (int j = 0; j < 8; j++) {
            float2 h = upk(fhi[j]), l = upk(flo[j]);
            fsd[(2*j)   * FSTR + px] =
                ((double)__fadd_rn(h.x, -OFFSET_F) + (double)l.x) + (double)fbs[2*j];
            fsd[(2*j+1) * FSTR + px] =
                ((double)__fadd_rn(h.y, -OFFSET_F) + (double)l.y) + (double)fbs[2*j+1];
        }
    } else {
        unsigned long long acc[8];
        #pragma unroll
        for (int j = 0; j < 8; j++) acc[j] = 0ull;
        #pragma unroll 8
        for (int c = 0; c < CIN; c++) {
            float xv = __ldg(xa + (size_t)c * HW);
            unsigned long long xd = pk2(xv, xv);
            const ulonglong2* wr = (const ulonglong2*)(wsv2 + c * 16);
            #pragma unroll
            for (int j = 0; j < 4; j++) {
                ulonglong2 a = wr[j];
                acc[2*j]   = ffma2(xd, a.x, acc[2*j]);
                acc[2*j+1] = ffma2(xd, a.y, acc[2*j+1]);
            }
        }
        #pragma unroll
        for (int j = 0; j < 8; j++) {
            float2 v = upk(acc[j]);
            vs[(2*j)   * FSTR + px] = v.x + vbs[2*j];
            vs[(2*j+1) * FSTR + px] = v.y + vbs[2*j+1];
        }
    }
    __syncthreads();

    // pooling: fp64 centers + fp32 value centers
    for (int it = t; it < 1568; it += NTHR) {
        int half = it >= 784;
        int rem = half ? it - 784 : it;
        int m = rem >> 4, cc = rem & 15;
        int i = m / 7, jj = m - i * 7;
        if (half) {
            float ssum = 0.f;
            for (int r = SEG_S[i]; r < SEG_E[i]; r++)
                for (int q = SEG_S[jj]; q < SEG_E[jj]; q++)
                    ssum += vs[cc * FSTR + r * 16 + q];
            vc[rem] = ssum * SEG_I[i] * SEG_I[jj];
        } else {
            double ssum = 0.0;
            for (int r = SEG_S[i]; r < SEG_E[i]; r++)
                for (int q = SEG_S[jj]; q < SEG_E[jj]; q++)
                    ssum += fsd[cc * FSTR + r * 16 + q];
            cfd[rem] = ssum * (double)SEG_I[i] * (double)SEG_I[jj];
        }
    }
    __syncthreads();

    if (t < 49) {
        double ss = 0.0;
        #pragma unroll
        for (int cc = 0; cc < 16; cc++) { double v = cfd[t*16+cc]; ss = fma(v, v, ss); }
        double inv = 1.0 / fmax(sqrt(ss), 1e-12);
        #pragma unroll
        for (int cc = 0; cc < 16; cc++) {
            double nv = cfd[t*16+cc] * inv;
            cfd[t*16+cc]  = nv;
            cf32[t*16+cc] = (float)nv;
        }
    }
    __syncthreads();

    // exact selection per pixel (lower 256 threads)
    float s = 0.f;
    int bm = 0;
    if (t < 256) {
        double invf;
        float ffn[16];
        {
            double ss = 0.0;
            #pragma unroll
            for (int cc = 0; cc < 16; cc++) {
                double v = fsd[cc * FSTR + t];
                ss = fma(v, v, ss);
            }
            invf = 1.0 / fmax(sqrt(ss), 1e-12);
            #pragma unroll
            for (int cc = 0; cc < 16; cc++)
                ffn[cc] = (float)(fsd[cc * FSTR + t] * invf);
        }
        const double alpha = (double)__ldg(salpha);
        const double beta  = (double)__ldg(sbeta);

        float mx32 = -1e30f;
        for (int m = 0; m < 49; m++) {
            const float4* cr = (const float4*)(cf32 + m * 16);
            float dot = 0.f;
            #pragma unroll
            for (int q = 0; q < 4; q++) {
                float4 w = cr[q];
                dot = __fmaf_rn(w.x, ffn[4*q+0], dot);
                dot = __fmaf_rn(w.y, ffn[4*q+1], dot);
                dot = __fmaf_rn(w.z, ffn[4*q+2], dot);
                dot = __fmaf_rn(w.w, ffn[4*q+3], dot);
            }
            mx32 = fmaxf(mx32, dot);
        }
        const float thr = mx32 - 1e-4f;
        double dz1 = -1e300, dz2 = -1e300, dz3 = -1e300;
        int m1 = 0, m2 = 0, m3 = 0;
        for (int m = 0; m < 49; m++) {
            const float4* cr = (const float4*)(cf32 + m * 16);
            float dot = 0.f;
            #pragma unroll
            for (int q = 0; q < 4; q++) {
                float4 w = cr[q];
                dot = __fmaf_rn(w.x, ffn[4*q+0], dot);
                dot = __fmaf_rn(w.y, ffn[4*q+1], dot);
                dot = __fmaf_rn(w.z, ffn[4*q+2], dot);
                dot = __fmaf_rn(w.w, ffn[4*q+3], dot);
            }
            if (dot >= thr) {
                double dd = 0.0;
                #pragma unroll
                for (int cc = 0; cc < 16; cc++)
                    dd = fma(cfd[m*16+cc], fsd[cc * FSTR + t], dd);
                double z = beta + alpha * (dd * invf);
                if (z > dz1)      { dz3 = dz2; m3 = m2; dz2 = dz1; m2 = m1; dz1 = z; m1 = m; }
                else if (z > dz2) { dz3 = dz2; m3 = m2; dz2 = z;  m2 = m; }
                else if (z > dz3) { dz3 = z;  m3 = m; }
            }
        }
        float s1f = (float)(1.0 / (1.0 + exp(-dz1)));
        bm = m1;
        if (dz1 - dz2 < 1e-5) {
            float s2f = (float)(1.0 / (1.0 + exp(-dz2)));
            if (s2f == s1f && m2 < bm) bm = m2;
            if (dz1 - dz3 < 1e-5) {
                float s3f = (float)(1.0 / (1.0 + exp(-dz3)));
                if (s3f == s1f && m3 < bm) bm = m3;
            }
        }
        s = s1f;

        atomicAdd(&agd[bm], s);
        #pragma unroll
        for (int cc = 0; cc < 16; cc++)
            atomicAdd(&agn[bm * 16 + cc], s * vs[cc * FSTR + t]);
    }
    __syncthreads();

    for (int it = t; it < 784; it += NTHR) {
        int m = it >> 4;
        g_agg[(size_t)b * 784 + it] = (agn[it] + vc[it]) / (agd[m] + 1.f);
    }
    if (t < 256) {
        g_sv[b * 256 + t] = s;
        g_bm[b * 256 + t] = bm;
    }
}

// ---- Kernel 2: P = agg @ pw^T per block; y[o][n] = s_n * P[bm_n][o] + pb[o] ----
#define PSTR 261
#define K2_OFF_P    0
#define K2_OFF_AGG  ((K2_OFF_P + 49*PSTR*4 + 15) & ~15)
#define K2_OFF_SV   ((K2_OFF_AGG + 784*4 + 15) & ~15)
#define K2_OFF_BM   ((K2_OFF_SV + 256*4 + 15) & ~15)
#define K2_OFF_PBS  ((K2_OFF_BM + 256*4 + 15) & ~15)
#define SMEM2_BYTES (K2_OFF_PBS + 256*4)

extern "C" __global__ void __launch_bounds__(NTHR, 2)
lc_k2(const float* __restrict__ pw, const float* __restrict__ pbg,
      float* __restrict__ out)
{
    extern __shared__ char smraw[];
    float* Pm  = (float*)(smraw + K2_OFF_P);
    float* agg = (float*)(smraw + K2_OFF_AGG);
    float* sv  = (float*)(smraw + K2_OFF_SV);
    int*   bmv = (int*)(smraw + K2_OFF_BM);
    float* pbs = (float*)(smraw + K2_OFF_PBS);

    const int t = threadIdx.x;
    const int b = blockIdx.x;
    const int batch = b / 49;
    const int g = b - batch * 49;
    const int gx = g / 7, gy = g - (g / 7) * 7;

    for (int i = t; i < 784; i += NTHR) agg[i] = g_agg[(size_t)b * 784 + i];
    if (t < 256) {
        sv[t]  = g_sv[b * 256 + t];
        bmv[t] = g_bm[b * 256 + t];
        pbs[t] = pbg[t];
    }
    __syncthreads();

    {
        const int o = t & 255, mh = t >> 8;
        const float4* wrow = (const float4*)(pw + o * 16);
        float4 w0 = __ldg(wrow), w1 = __ldg(wrow + 1);
        float4 w2 = __ldg(wrow + 2), w3 = __ldg(wrow + 3);
        const int m0 = mh ? 25 : 0, m1 = mh ? 49 : 25;
        for (int m = m0; m < m1; m++) {
            const float4* ar = (const float4*)(agg + m * 16);
            float4 a0 = ar[0], a1 = ar[1], a2 = ar[2], a3 = ar[3];
            float dot = 0.f;
            dot = __fmaf_rn(w0.x, a0.x, dot); dot = __fmaf_rn(w0.y, a0.y, dot);
            dot = __fmaf_rn(w0.z, a0.z, dot); dot = __fmaf_rn(w0.w, a0.w, dot);
            dot = __fmaf_rn(w1.x, a1.x, dot); dot = __fmaf_rn(w1.y, a1.y, dot);
            dot = __fmaf_rn(w1.z, a1.z, dot); dot = __fmaf_rn(w1.w, a1.w, dot);
            dot = __fmaf_rn(w2.x, a2.x, dot); dot = __fmaf_rn(w2.y, a2.y, dot);
            dot = __fmaf_rn(w2.z, a2.z, dot); dot = __fmaf_rn(w2.w, a2.w, dot);
            dot = __fmaf_rn(w3.x, a3.x, dot); dot = __fmaf_rn(w3.y, a3.y, dot);
            dot = __fmaf_rn(w3.z, a3.z, dot); dot = __fmaf_rn(w3.w, a3.w, dot);
            Pm[m * PSTR + o] = dot;
        }
    }
    __syncthreads();

    {
        const int nid = t & 127, oid = t >> 7;
        const int n0 = 2 * nid;
        const float s0 = sv[n0], s1 = sv[n0 + 1];
        const float* P0 = Pm + bmv[n0] * PSTR;
        const float* P1 = Pm + bmv[n0 + 1] * PSTR;
        float* yb = out + (size_t)batch * COUT * HW
                        + (size_t)(gx * 16 + (n0 >> 4)) * WIDTH + (gy * 16 + (n0 & 15));
        const int obase = oid << 6;
        #pragma unroll 8
        for (int i = 0; i < 64; i++) {
            const int o = obase + i;
            float pbv = pbs[o];
            float2 r;
            r.x = __fmaf_rn(s0, P0[o], pbv);
            r.y = __fmaf_rn(s1, P1[o], pbv);
            *(float2*)(yb + (size_t)o * HW) = r;
        }
    }
}

extern "C" void kernel_launch(void* const* d_in, const int* in_sizes, int n_in,
                              void* d_out, int out_size) {
    const float* x   = (const float*)d_in[0];
    const float* fw  = (const float*)d_in[1];
    const float* fb  = (const float*)d_in[2];
    const float* vw  = (const float*)d_in[3];
    const float* vb  = (const float*)d_in[4];
    const float* pw  = (const float*)d_in[5];
    const float* pb  = (const float*)d_in[6];
    const float* sa  = (const float*)d_in[7];
    const float* sb  = (const float*)d_in[8];
    float* out = (float*)d_out;

    cudaFuncSetAttribute(lc_k1, cudaFuncAttributeMaxDynamicSharedMemorySize,
                         SMEM1_BYTES);
    cudaFuncSetAttribute(lc_k1b, cudaFuncAttributeMaxDynamicSharedMemorySize,
                         SMEM1B_BYTES);
    cudaFuncSetAttribute(lc_k2, cudaFuncAttributeMaxDynamicSharedMemorySize,
                         SMEM2_BYTES);
    lc_k1<<<NBLK, NTHR, SMEM1_BYTES>>>(x, fw, fb, vw, vb, sa, sb);
    lc_k1b<<<NBLK, NTHR, SMEM1B_BYTES>>>(x, fw, fb, vw, vb, sa, sb);
    lc_k2<<<NBLK, NTHR, SMEM2_BYTES>>>(pw, pb, out);
}

// round 17
// speedup vs baseline: 1.0738x; 1.0738x over previous
#include <cuda_runtime.h>
#include <math.h>

// Problem constants
#define CIN    128
#define CMID   16
#define COUT   256
#define HW     12544
#define WIDTH  112
#define NBLK   784
#define NTHR   512

// Pooling segments 16 -> 7 (overlapping avg pool)
__constant__ int   SEG_S[7] = {0, 2, 4, 6, 9, 11, 13};
__constant__ int   SEG_E[7] = {3, 5, 7, 10, 12, 14, 16};
__constant__ float SEG_I[7] = {1.f/3.f, 1.f/3.f, 1.f/3.f, 0.25f, 1.f/3.f, 1.f/3.f, 1.f/3.f};

// Inter-kernel scratch (static device allocations — allowed)
__device__ float g_agg[NBLK * 784];   // merged agg per block  [49][16]
__device__ float g_sv [NBLK * 256];   // per-pixel sigmoid
__device__ int   g_bm [NBLK * 256];   // per-pixel argmax cluster
__device__ int   g_flag[NBLK];        // 1 = block needs exact recheck
__device__ float g_vs [NBLK * 4096];  // stashed v features [cc][px] per block

// ---- packed f32x2 helpers (sm_103a, PTX-only) ----
__device__ __forceinline__ unsigned long long pk2(float a, float b) {
    unsigned long long r;
    asm("mov.b64 %0, {%1, %2};" : "=l"(r) : "f"(a), "f"(b));
    return r;
}
__device__ __forceinline__ unsigned long long ffma2(unsigned long long a,
                                                    unsigned long long b,
                                                    unsigned long long c) {
    unsigned long long d;
    asm("fma.rn.f32x2 %0, %1, %2, %3;" : "=l"(d) : "l"(a), "l"(b), "l"(c));
    return d;
}
__device__ __forceinline__ unsigned long long fmul2(unsigned long long a,
                                                    unsigned long long b) {
    unsigned long long d;
    asm("mul.rn.f32x2 %0, %1, %2;" : "=l"(d) : "l"(a), "l"(b));
    return d;
}
__device__ __forceinline__ unsigned long long fadd2(unsigned long long a,
                                                    unsigned long long b) {
    unsigned long long d;
    asm("add.rn.f32x2 %0, %1, %2;" : "=l"(d) : "l"(a), "l"(b));
    return d;
}
__device__ __forceinline__ float2 upk(unsigned long long v) {
    float2 f;
    asm("mov.b64 {%0, %1}, %2;" : "=f"(f.x), "=f"(f.y) : "l"(v));
    return f;
}

#define SGNMASK 0x8000000080000000ULL
#define OFFSET_F 16384.0f

// Exact compensated accumulate (K1b only).
__device__ __forceinline__ void dfacc2(unsigned long long& hi, unsigned long long& lo,
                                       unsigned long long xd, unsigned long long w) {
    unsigned long long ph = fmul2(xd, w);
    unsigned long long pl = ffma2(xd, w, ph ^ SGNMASK);
    unsigned long long s  = fadd2(hi, ph);
    unsigned long long d  = fadd2(hi, s ^ SGNMASK);
    unsigned long long e  = fadd2(d, ph);
    lo = fadd2(lo, fadd2(e, pl));
    hi = s;
}

#define FSTR 257

// ================= Kernel 1: fp32 common path (3 CTAs/SM) =================
#define A_FS   0                       // float[16*257]
#define A_VS   (A_FS  + 16*FSTR)       // float[16*257]
#define A_WBUF (A_VS  + 16*FSTR)       // float[4096]: wsf/wsv -> vc/cf32
#define A_AGN  (A_WBUF + 4096)         // float[784]
#define A_AGD  (A_AGN + 784)           // float[52]
#define A_FBS  (A_AGD + 52)            // float[16]
#define A_VBS  (A_FBS + 16)            // float[16]
#define A_ZB1  (A_VBS + 16)            // float[512]
#define A_ZB2  (A_ZB1 + 512)           // float[512]
#define A_BMB  (A_ZB2 + 512)           // int[512]
#define SMEM1_BYTES ((A_BMB + 512) * 4)   // 58,896 B -> 3 CTAs/SM

extern "C" __global__ void __launch_bounds__(NTHR, 3)
lc_k1(const float* __restrict__ x,   const float* __restrict__ fw,
      const float* __restrict__ fb,  const float* __restrict__ vw,
      const float* __restrict__ vb,  const float* __restrict__ salpha,
      const float* __restrict__ sbeta)
{
    extern __shared__ float sm[];
    float* fs   = sm + A_FS;
    float* vs   = sm + A_VS;
    float* wbuf = sm + A_WBUF;
    float* agn  = sm + A_AGN;
    float* agd  = sm + A_AGD;
    float* fbs  = sm + A_FBS;
    float* vbs  = sm + A_VBS;
    float* zb1  = sm + A_ZB1;
    float* zb2  = sm + A_ZB2;
    int*   bmb  = (int*)(sm + A_BMB);
    float* wsf  = wbuf;
    float* wsv  = wbuf + 2048;
    float* vc   = wbuf;
    float* cf32 = wbuf + 784;

    const int t = threadIdx.x;
    const int b = blockIdx.x;
    const int batch = b / 49;
    const int g = b - batch * 49;
    const int gx = g / 7, gy = g - (g / 7) * 7;

    for (int i = t; i < 2048; i += NTHR) {
        int c = i >> 4, o = i & 15;
        wsf[i] = fw[o * CIN + c];
        wsv[i] = vw[o * CIN + c];
    }
    if (t < 16) { fbs[t] = fb[t]; vbs[t] = vb[t]; }
    for (int i = t; i < 784; i += NTHR) agn[i] = 0.f;
    if (t < 49) agd[t] = 0.f;
    __syncthreads();

    // ---- Stage A: warps 0-7 -> f, warps 8-15 -> v (1 pixel, 128 ch each) ----
    const int px  = t & 255;
    const int prj = t >> 8;
    const int apr = px >> 4, apc = px & 15;
    const float* xa = x + (size_t)batch * COUT * HW + (size_t)prj * CIN * HW
                        + (size_t)(gx * 16 + apr) * WIDTH + (gy * 16 + apc);
    const float* wsel = prj ? wsv : wsf;
    {
        unsigned long long acc[8];
        #pragma unroll
        for (int j = 0; j < 8; j++) acc[j] = 0ull;
        #pragma unroll 8
        for (int c = 0; c < CIN; c++) {
            float xv = __ldg(xa + (size_t)c * HW);
            unsigned long long xd = pk2(xv, xv);
            const ulonglong2* wr = (const ulonglong2*)(wsel + c * 16);
            #pragma unroll
            for (int j = 0; j < 4; j++) {
                ulonglong2 a = wr[j];
                acc[2*j]   = ffma2(xd, a.x, acc[2*j]);
                acc[2*j+1] = ffma2(xd, a.y, acc[2*j+1]);
            }
        }
        float* dst = prj ? vs : fs;
        const float* bsel = prj ? vbs : fbs;
        #pragma unroll
        for (int j = 0; j < 8; j++) {
            float2 v = upk(acc[j]);
            dst[(2*j)   * FSTR + px] = v.x + bsel[2*j];
            dst[(2*j+1) * FSTR + px] = v.y + bsel[2*j+1];
        }
    }
    __syncthreads();

    // ---- Stage B: fp32 pooling ----
    for (int it = t; it < 1568; it += NTHR) {
        int half = it >= 784;
        int rem = half ? it - 784 : it;
        int m = rem >> 4, cc = rem & 15;
        int i = m / 7, jj = m - i * 7;
        const float* src = half ? vs : fs;
        float ssum = 0.f;
        for (int r = SEG_S[i]; r < SEG_E[i]; r++)
            for (int q = SEG_S[jj]; q < SEG_E[jj]; q++)
                ssum += src[cc * FSTR + r * 16 + q];
        ssum *= SEG_I[i] * SEG_I[jj];
        if (half) vc[rem] = ssum; else cf32[rem] = ssum;
    }
    __syncthreads();

    if (t < 49) {
        float ss = 0.f;
        #pragma unroll
        for (int cc = 0; cc < 16; cc++) {
            float v = cf32[t*16+cc];
            ss = __fmaf_rn(v, v, ss);
        }
        float inv = 1.f / fmaxf(sqrtf(ss), 1e-12f);
        #pragma unroll
        for (int cc = 0; cc < 16; cc++) cf32[t*16+cc] *= inv;
    }
    __syncthreads();

    // ---- Stage C: split-cluster scan (all 512 threads) ----
    const float alphaf = __ldg(salpha);
    const float betaf  = __ldg(sbeta);
    {
        float ffn[16];
        float ss = 0.f;
        #pragma unroll
        for (int cc = 0; cc < 16; cc++) {
            float v = fs[cc * FSTR + px];
            ffn[cc] = v;
            ss = __fmaf_rn(v, v, ss);
        }
        float inv = 1.f / fmaxf(sqrtf(ss), 1e-12f);
        #pragma unroll
        for (int cc = 0; cc < 16; cc++) ffn[cc] *= inv;

        float z1h = -1e30f, z2h = -1e30f;
        int bmh = 0;
        const int mstart = prj ? 25 : 0;
        const int mend   = prj ? 49 : 25;
        for (int m = mstart; m < mend; m++) {
            const float4* cr = (const float4*)(cf32 + m * 16);
            float dot = 0.f;
            #pragma unroll
            for (int q = 0; q < 4; q++) {
                float4 w = cr[q];
                dot = __fmaf_rn(w.x, ffn[4*q+0], dot);
                dot = __fmaf_rn(w.y, ffn[4*q+1], dot);
                dot = __fmaf_rn(w.z, ffn[4*q+2], dot);
                dot = __fmaf_rn(w.w, ffn[4*q+3], dot);
            }
            float z = betaf + alphaf * dot;
            if (z > z1h) { z2h = z1h; z1h = z; bmh = m; }
            else if (z > z2h) { z2h = z; }
        }
        zb1[t] = z1h; zb2[t] = z2h; bmb[t] = bmh;
    }
    __syncthreads();

    float z1 = 1e30f, z2 = 0.f;
    int bm = 0;
    float s = 0.f;
    if (t < 256) {
        float a1 = zb1[t],       a2 = zb2[t];       int abm = bmb[t];
        float b1 = zb1[t + 256], b2 = zb2[t + 256]; int bbm = bmb[t + 256];
        if (a1 >= b1) { z1 = a1; bm = abm; z2 = fmaxf(a2, b1); }
        else          { z1 = b1; bm = bbm; z2 = fmaxf(b2, a1); }
        s = 1.f / (1.f + expf(-z1));
    }

    // ---- vote -> flag (exact recheck handled by lc_k1b) ----
    int risk = __syncthreads_or((t < 256) && (z1 - z2) < 1e-4f);
    if (t == 0) g_flag[b] = risk;

    // ---- share (s, bm); split atomics ----
    if (t < 256) { zb1[t] = s; bmb[t] = bm; }
    __syncthreads();
    {
        float sv = zb1[px];
        int bmv = bmb[px];
        if (t < 256) atomicAdd(&agd[bmv], sv);
        const int cc0 = prj ? 8 : 0;
        #pragma unroll
        for (int cc = 0; cc < 8; cc++)
            atomicAdd(&agn[bmv * 16 + cc0 + cc], sv * vs[(cc0 + cc) * FSTR + px]);
    }
    __syncthreads();

    for (int it = t; it < 784; it += NTHR) {
        int m = it >> 4;
        g_agg[(size_t)b * 784 + it] = (agn[it] + vc[it]) / (agd[m] + 1.f);
    }
    // stash v features for K1b (bit-identical replay)
    for (int i = t; i < 4096; i += NTHR)
        g_vs[(size_t)b * 4096 + i] = vs[(i >> 8) * FSTR + (i & 255)];
    if (t < 256) {
        g_sv[b * 256 + t] = s;
        g_bm[b * 256 + t] = bm;
    }
}

// ============ Kernel 1b: exact recheck for flagged blocks only ============
// All 512 threads split the exact f projection (2 threads / pixel, c-halves).
#define B_FSD  0                               // double[16*257] = 32,896
#define B_CFD  (B_FSD + 16*FSTR*8)             // double[784]
#define B_FW   (B_CFD + 784*8)                 // float[2048]  f weights only
#define B_VS   (B_FW  + 2048*4)                // float[16*257] staged v features
#define B_VC   (B_VS  + 16*FSTR*4)             // float[784]
#define B_CF32 (B_VC  + 784*4)                 // float[784]
#define B_AGN  (B_CF32 + 784*4)                // float[784]
#define B_AGD  (B_AGN + 784*4)                 // float[52]
#define B_FBS  (B_AGD + 52*4)                  // float[16]
#define SMEM1B_BYTES (B_FBS + 16*4)            // ~73.6 KB

extern "C" __global__ void __launch_bounds__(NTHR, 2)
lc_k1b(const float* __restrict__ x,   const float* __restrict__ fw,
       const float* __restrict__ fb,  const float* __restrict__ salpha,
       const float* __restrict__ sbeta)
{
    const int b = blockIdx.x;
    if (g_flag[b] == 0) return;       // uniform across the CTA; no syncs yet

    extern __shared__ char smraw[];
    double* fsd  = (double*)(smraw + B_FSD);
    double* cfd  = (double*)(smraw + B_CFD);
    float*  fw2  = (float*)(smraw + B_FW);
    float*  vs   = (float*)(smraw + B_VS);
    float*  vc   = (float*)(smraw + B_VC);
    float*  cf32 = (float*)(smraw + B_CF32);
    float*  agn  = (float*)(smraw + B_AGN);
    float*  agd  = (float*)(smraw + B_AGD);
    float*  fbs  = (float*)(smraw + B_FBS);

    const int t = threadIdx.x;
    const int batch = b / 49;
    const int g = b - batch * 49;
    const int gx = g / 7, gy = g - (g / 7) * 7;
    const int px    = t & 255;
    const int chalf = t >> 8;          // c-half for exact f
    const int apr = px >> 4, apc = px & 15;

    for (int i = t; i < 2048; i += NTHR) {
        int c = i >> 4, o = i & 15;
        fw2[i] = fw[o * CIN + c];
    }
    // stage v features from K1's stash (bit-identical)
    for (int i = t; i < 4096; i += NTHR)
        vs[(i >> 8) * FSTR + (i & 255)] = g_vs[(size_t)b * 4096 + i];
    if (t < 16) fbs[t] = fb[t];
    for (int i = t; i < 784; i += NTHR) agn[i] = 0.f;
    if (t < 49) agd[t] = 0.f;
    __syncthreads();

    // exact f: 2 threads per pixel, 64 channels each (offset-fast2sum partials)
    {
        const float* xf = x + (size_t)batch * COUT * HW
                            + (size_t)(gx * 16 + apr) * WIDTH + (gy * 16 + apc);
        const int c0 = chalf << 6;
        unsigned long long fhi[8], flo[8];
        #pragma unroll
        for (int j = 0; j < 8; j++) { fhi[j] = pk2(OFFSET_F, OFFSET_F); flo[j] = 0ull; }
        #pragma unroll 4
        for (int ci = 0; ci < 64; ci++) {
            const int c = c0 + ci;
            float x1 = __ldg(xf + (size_t)c * HW);
            unsigned long long x1d = pk2(x1, x1);
            const ulonglong2* wf = (const ulonglong2*)(fw2 + c * 16);
            #pragma unroll
            for (int j = 0; j < 4; j++) {
                ulonglong2 a = wf[j];
                dfacc2(fhi[2*j],   flo[2*j],   x1d, a.x);
                dfacc2(fhi[2*j+1], flo[2*j+1], x1d, a.y);
            }
        }
        if (chalf == 1) {
            #pragma unroll
            for (int j = 0; j < 8; j++) {
                float2 h = upk(fhi[j]), l = upk(flo[j]);
                fsd[(2*j)   * FSTR + px] =
                    (double)__fadd_rn(h.x, -OFFSET_F) + (double)l.x;
                fsd[(2*j+1) * FSTR + px] =
                    (double)__fadd_rn(h.y, -OFFSET_F) + (double)l.y;
            }
        }
        __syncthreads();
        if (chalf == 0) {
            #pragma unroll
            for (int j = 0; j < 8; j++) {
                float2 h = upk(fhi[j]), l = upk(flo[j]);
                double p0 = (double)__fadd_rn(h.x, -OFFSET_F) + (double)l.x;
                double p1 = (double)__fadd_rn(h.y, -OFFSET_F) + (double)l.y;
                fsd[(2*j)   * FSTR + px] =
                    (fsd[(2*j)   * FSTR + px] + p0) + (double)fbs[2*j];
                fsd[(2*j+1) * FSTR + px] =
                    (fsd[(2*j+1) * FSTR + px] + p1) + (double)fbs[2*j+1];
            }
        }
    }
    __syncthreads();

    // pooling: fp64 centers + fp32 value centers
    for (int it = t; it < 1568; it += NTHR) {
        int half = it >= 784;
        int rem = half ? it - 784 : it;
        int m = rem >> 4, cc = rem & 15;
        int i = m / 7, jj = m - i * 7;
        if (half) {
            float ssum = 0.f;
            for (int r = SEG_S[i]; r < SEG_E[i]; r++)
                for (int q = SEG_S[jj]; q < SEG_E[jj]; q++)
                    ssum += vs[cc * FSTR + r * 16 + q];
            vc[rem] = ssum * SEG_I[i] * SEG_I[jj];
        } else {
            double ssum = 0.0;
            for (int r = SEG_S[i]; r < SEG_E[i]; r++)
                for (int q = SEG_S[jj]; q < SEG_E[jj]; q++)
                    ssum += fsd[cc * FSTR + r * 16 + q];
            cfd[rem] = ssum * (double)SEG_I[i] * (double)SEG_I[jj];
        }
    }
    __syncthreads();

    if (t < 49) {
        double ss = 0.0;
        #pragma unroll
        for (int cc = 0; cc < 16; cc++) { double v = cfd[t*16+cc]; ss = fma(v, v, ss); }
        double inv = 1.0 / fmax(sqrt(ss), 1e-12);
        #pragma unroll
        for (int cc = 0; cc < 16; cc++) {
            double nv = cfd[t*16+cc] * inv;
            cfd[t*16+cc]  = nv;
            cf32[t*16+cc] = (float)nv;
        }
    }
    __syncthreads();

    // exact selection per pixel (lower 256 threads)
    float s = 0.f;
    int bm = 0;
    if (t < 256) {
        double invf;
        float ffn[16];
        {
            double ss = 0.0;
            #pragma unroll
            for (int cc = 0; cc < 16; cc++) {
                double v = fsd[cc * FSTR + t];
                ss = fma(v, v, ss);
            }
            invf = 1.0 / fmax(sqrt(ss), 1e-12);
            #pragma unroll
            for (int cc = 0; cc < 16; cc++)
                ffn[cc] = (float)(fsd[cc * FSTR + t] * invf);
        }
        const double alpha = (double)__ldg(salpha);
        const double beta  = (double)__ldg(sbeta);

        float mx32 = -1e30f;
        for (int m = 0; m < 49; m++) {
            const float4* cr = (const float4*)(cf32 + m * 16);
            float dot = 0.f;
            #pragma unroll
            for (int q = 0; q < 4; q++) {
                float4 w = cr[q];
                dot = __fmaf_rn(w.x, ffn[4*q+0], dot);
                dot = __fmaf_rn(w.y, ffn[4*q+1], dot);
                dot = __fmaf_rn(w.z, ffn[4*q+2], dot);
                dot = __fmaf_rn(w.w, ffn[4*q+3], dot);
            }
            mx32 = fmaxf(mx32, dot);
        }
        const float thr = mx32 - 1e-4f;
        double dz1 = -1e300, dz2 = -1e300, dz3 = -1e300;
        int m1 = 0, m2 = 0, m3 = 0;
        for (int m = 0; m < 49; m++) {
            const float4* cr = (const float4*)(cf32 + m * 16);
            float dot = 0.f;
            #pragma unroll
            for (int q = 0; q < 4; q++) {
                float4 w = cr[q];
                dot = __fmaf_rn(w.x, ffn[4*q+0], dot);
                dot = __fmaf_rn(w.y, ffn[4*q+1], dot);
                dot = __fmaf_rn(w.z, ffn[4*q+2], dot);
                dot = __fmaf_rn(w.w, ffn[4*q+3], dot);
            }
            if (dot >= thr) {
                double dd = 0.0;
                #pragma unroll
                for (int cc = 0; cc < 16; cc++)
                    dd = fma(cfd[m*16+cc], fsd[cc * FSTR + t], dd);
                double z = beta + alpha * (dd * invf);
                if (z > dz1)      { dz3 = dz2; m3 = m2; dz2 = dz1; m2 = m1; dz1 = z; m1 = m; }
                else if (z > dz2) { dz3 = dz2; m3 = m2; dz2 = z;  m2 = m; }
                else if (z > dz3) { dz3 = z;  m3 = m; }
            }
        }
        float s1f = (float)(1.0 / (1.0 + exp(-dz1)));
        bm = m1;
        if (dz1 - dz2 < 1e-5) {
            float s2f = (float)(1.0 / (1.0 + exp(-dz2)));
            if (s2f == s1f && m2 < bm) bm = m2;
            if (dz1 - dz3 < 1e-5) {
                float s3f = (float)(1.0 / (1.0 + exp(-dz3)));
                if (s3f == s1f && m3 < bm) bm = m3;
            }
        }
        s = s1f;

        atomicAdd(&agd[bm], s);
        #pragma unroll
        for (int cc = 0; cc < 16; cc++)
            atomicAdd(&agn[bm * 16 + cc], s * vs[cc * FSTR + t]);
    }
    __syncthreads();

    for (int it = t; it < 784; it += NTHR) {
        int m = it >> 4;
        g_agg[(size_t)b * 784 + it] = (agn[it] + vc[it]) / (agd[m] + 1.f);
    }
    if (t < 256) {
        g_sv[b * 256 + t] = s;
        g_bm[b * 256 + t] = bm;
    }
}

// ---- Kernel 2: P = agg @ pw^T per block; y[o][n] = s_n * P[bm_n][o] + pb[o] ----
#define PSTR 261
#define K2_OFF_P    0
#define K2_OFF_AGG  ((K2_OFF_P + 49*PSTR*4 + 15) & ~15)
#define K2_OFF_SV   ((K2_OFF_AGG + 784*4 + 15) & ~15)
#define K2_OFF_BM   ((K2_OFF_SV + 256*4 + 15) & ~15)
#define K2_OFF_PBS  ((K2_OFF_BM + 256*4 + 15) & ~15)
#define SMEM2_BYTES (K2_OFF_PBS + 256*4)

extern "C" __global__ void __launch_bounds__(NTHR, 2)
lc_k2(const float* __restrict__ pw, const float* __restrict__ pbg,
      float* __restrict__ out)
{
    extern __shared__ char smraw[];
    float* Pm  = (float*)(smraw + K2_OFF_P);
    float* agg = (float*)(smraw + K2_OFF_AGG);
    float* sv  = (float*)(smraw + K2_OFF_SV);
    int*   bmv = (int*)(smraw + K2_OFF_BM);
    float* pbs = (float*)(smraw + K2_OFF_PBS);

    const int t = threadIdx.x;
    const int b = blockIdx.x;
    const int batch = b / 49;
    const int g = b - batch * 49;
    const int gx = g / 7, gy = g - (g / 7) * 7;

    for (int i = t; i < 784; i += NTHR) agg[i] = g_agg[(size_t)b * 784 + i];
    if (t < 256) {
        sv[t]  = g_sv[b * 256 + t];
        bmv[t] = g_bm[b * 256 + t];
        pbs[t] = pbg[t];
    }
    __syncthreads();

    {
        const int o = t & 255, mh = t >> 8;
        const float4* wrow = (const float4*)(pw + o * 16);
        float4 w0 = __ldg(wrow), w1 = __ldg(wrow + 1);
        float4 w2 = __ldg(wrow + 2), w3 = __ldg(wrow + 3);
        const int m0 = mh ? 25 : 0, m1 = mh ? 49 : 25;
        for (int m = m0; m < m1; m++) {
            const float4* ar = (const float4*)(agg + m * 16);
            float4 a0 = ar[0], a1 = ar[1], a2 = ar[2], a3 = ar[3];
            float dot = 0.f;
            dot = __fmaf_rn(w0.x, a0.x, dot); dot = __fmaf_rn(w0.y, a0.y, dot);
            dot = __fmaf_rn(w0.z, a0.z, dot); dot = __fmaf_rn(w0.w, a0.w, dot);
            dot = __fmaf_rn(w1.x, a1.x, dot); dot = __fmaf_rn(w1.y, a1.y, dot);
            dot = __fmaf_rn(w1.z, a1.z, dot); dot = __fmaf_rn(w1.w, a1.w, dot);
            dot = __fmaf_rn(w2.x, a2.x, dot); dot = __fmaf_rn(w2.y, a2.y, dot);
            dot = __fmaf_rn(w2.z, a2.z, dot); dot = __fmaf_rn(w2.w, a2.w, dot);
            dot = __fmaf_rn(w3.x, a3.x, dot); dot = __fmaf_rn(w3.y, a3.y, dot);
            dot = __fmaf_rn(w3.z, a3.z, dot); dot = __fmaf_rn(w3.w, a3.w, dot);
            Pm[m * PSTR + o] = dot;
        }
    }
    __syncthreads();

    {
        const int nid = t & 127, oid = t >> 7;
        const int n0 = 2 * nid;
        const float s0 = sv[n0], s1 = sv[n0 + 1];
        const float* P0 = Pm + bmv[n0] * PSTR;
        const float* P1 = Pm + bmv[n0 + 1] * PSTR;
        float* yb = out + (size_t)batch * COUT * HW
                        + (size_t)(gx * 16 + (n0 >> 4)) * WIDTH + (gy * 16 + (n0 & 15));
        const int obase = oid << 6;
        #pragma unroll 8
        for (int i = 0; i < 64; i++) {
            const int o = obase + i;
            float pbv = pbs[o];
            float2 r;
            r.x = __fmaf_rn(s0, P0[o], pbv);
            r.y = __fmaf_rn(s1, P1[o], pbv);
            *(float2*)(yb + (size_t)o * HW) = r;
        }
    }
}

extern "C" void kernel_launch(void* const* d_in, const int* in_sizes, int n_in,
                              void* d_out, int out_size) {
    const float* x   = (const float*)d_in[0];
    const float* fw  = (const float*)d_in[1];
    const float* fb  = (const float*)d_in[2];
    const float* vw  = (const float*)d_in[3];
    const float* vb  = (const float*)d_in[4];
    const float* pw  = (const float*)d_in[5];
    const float* pb  = (const float*)d_in[6];
    const float* sa  = (const float*)d_in[7];
    const float* sb  = (const float*)d_in[8];
    float* out = (float*)d_out;

    cudaFuncSetAttribute(lc_k1, cudaFuncAttributeMaxDynamicSharedMemorySize,
                         SMEM1_BYTES);
    cudaFuncSetAttribute(lc_k1b, cudaFuncAttributeMaxDynamicSharedMemorySize,
                         SMEM1B_BYTES);
    cudaFuncSetAttribute(lc_k2, cudaFuncAttributeMaxDynamicSharedMemorySize,
                         SMEM2_BYTES);
    lc_k1<<<NBLK, NTHR, SMEM1_BYTES>>>(x, fw, fb, vw, vb, sa, sb);
    lc_k1b<<<NBLK, NTHR, SMEM1B_BYTES>>>(x, fw, fb, sa, sb);
    lc_k2<<<NBLK, NTHR, SMEM2_BYTES>>>(pw, pb, out);
}